// round 14
// baseline (speedup 1.0000x reference)
#include <cuda_runtime.h>
#include <cuda_fp16.h>
#include <cstdint>

#define B_PTS   131072
#define HDIM    256
#define NBLK    8
#define NMID    3
#define MT      16
#define NTHREADS 256
#define NLAYERS (NBLK * NMID)

// tangent-state scaling (exact powers of two; divided out of J at the end)
#define TS_SEED   16384.f
#define TS_LAYER  16.f
#define TS_INV    (1.f / 67108864.f)   // 2^-26

// ---------------- shared memory byte map (per CTA, 2 CTAs/SM) ----------------
#define OFF_AHI  0            // A hi frags: 3mt x 16ks x 32lane x 16B = 24576
#define OFF_ALO  24576        // A lo frags (fp16 residual)            = 24576
#define OFF_WOS  49152        // 512 floats = 2048 B
#define OFF_ZX   51200        // 32 floats
#define OFF_VV   51328        // 32 floats
#define OFF_DL   51456        // 16 floats
#define OFF_RED  51520        // 192 floats = 768 B (2-half output reduction)
#define OFF_BM   52288        // staged mid-layer biases: 3 x 256 floats = 3072 B
#define SMEM_BYTES 55360

// prepacked B fragments: [layer][ks 16][ntile 32][lane 32] x uint4 {b0hi,b1hi,b0lo,b1lo}
__device__ uint4 g_Wf[(size_t)NLAYERS * 16 * 32 * 32];

// ---------------- helpers ----------------
__device__ __forceinline__ void mma_f16(float c[4], const uint4& a, uint32_t b0, uint32_t b1) {
    asm volatile("mma.sync.aligned.m16n8k16.row.col.f32.f16.f16.f32 "
                 "{%0,%1,%2,%3}, {%4,%5,%6,%7}, {%8,%9}, {%0,%1,%2,%3};"
                 : "+f"(c[0]), "+f"(c[1]), "+f"(c[2]), "+f"(c[3])
                 : "r"(a.x), "r"(a.y), "r"(a.z), "r"(a.w), "r"(b0), "r"(b1));
}
__device__ __forceinline__ uint32_t h2u(__half a, __half b) {
    __half2 h = __halves2half2(a, b);
    return *reinterpret_cast<uint32_t*>(&h);
}
// byte offset of element (row 0..47, k 0..255) inside one A image (hi or lo)
// rows 0-15 = h tile, 16-31 = t0, 32-47 = t1
__device__ __forceinline__ int abyte(int row, int k) {
    int tile = (row >> 4) * 16 + (k >> 4);
    int lane = ((row & 7) << 2) | ((k >> 1) & 3);
    int sub  = ((row & 8) >> 2) | ((k & 8) >> 1) | (k & 1);
    return tile * 512 + lane * 16 + sub * 2;
}
__device__ __forceinline__ void split_store(char* bhi, char* blo, int boff, float v) {
    __half h = __float2half_rn(v);
    __half l = __float2half_rn(v - __half2float(h));
    *(__half*)(bhi + boff) = h;
    *(__half*)(blo + boff) = l;
}

// ---------------- pre-pass: pack Wm into split fp16 B-fragment image ----------------
__global__ void prep_w_kernel(const float* __restrict__ Wm) {
    int g = blockIdx.x * 256 + threadIdx.x;     // 0 .. 393215
    int lane = g & 31;
    int t = g >> 5;
    int ntile = t & 31; t >>= 5;
    int ks    = t & 15; t >>= 4;
    int l     = t;
    int n  = ntile * 8 + (lane >> 2);
    int kb = ks * 16 + 2 * (lane & 3);
    const float* W = Wm + (size_t)l * HDIM * HDIM;
    __half hh[4], ll[4];
    int kk[4] = {kb, kb + 1, kb + 8, kb + 9};
    #pragma unroll
    for (int i = 0; i < 4; ++i) {
        float w = W[(size_t)kk[i] * HDIM + n];
        hh[i] = __float2half_rn(w);
        ll[i] = __float2half_rn(w - __half2float(hh[i]));
    }
    uint4 o;
    o.x = h2u(hh[0], hh[1]);
    o.y = h2u(hh[2], hh[3]);
    o.z = h2u(ll[0], ll[1]);
    o.w = h2u(ll[2], ll[3]);
    g_Wf[g] = o;
}

// ---------------- main kernel : 16 pts/CTA, 2 CTAs/SM ----------------
__global__ void __launch_bounds__(NTHREADS, 2)
eq_resflow_f16(const float* __restrict__ x,  const float* __restrict__ v,
               const float* __restrict__ Wi, const float* __restrict__ bi,
               const float* __restrict__ bm,
               const float* __restrict__ Wo, const float* __restrict__ bo,
               float* __restrict__ out)
{
    extern __shared__ char smem[];
    char* Ahi = smem + OFF_AHI;
    char* Alo = smem + OFF_ALO;
    float* Wos = (float*)(smem + OFF_WOS);
    float* zx  = (float*)(smem + OFF_ZX);
    float* vv  = (float*)(smem + OFF_VV);
    float* dl  = (float*)(smem + OFF_DL);
    float* red = (float*)(smem + OFF_RED);
    float* bms = (float*)(smem + OFF_BM);

    const int tid  = threadIdx.x;
    const int w    = tid >> 5;        // 0..7: n-group (4 ntiles each)
    const int lane = tid & 31;
    const int pbase = blockIdx.x * MT;

    if (tid < MT) {
        float2 xx = *reinterpret_cast<const float2*>(x + 2 * (pbase + tid));
        float2 vx = *reinterpret_cast<const float2*>(v + 2 * (pbase + tid));
        zx[2 * tid] = xx.x; zx[2 * tid + 1] = xx.y;
        vv[2 * tid] = vx.x; vv[2 * tid + 1] = vx.y;
        dl[tid] = 0.f;
    }
    __syncthreads();

    for (int b = 0; b < NBLK; ++b) {
        // ---------- layer 0 : 2 -> 256, split-write A frags; also stage bm biases ----------
        {
            int n = tid;
            float w0 = __ldg(Wi + (size_t)b * 2 * HDIM + n);
            float w1 = __ldg(Wi + (size_t)b * 2 * HDIM + HDIM + n);
            float bb = __ldg(bi + (size_t)b * HDIM + n);
            // stage this block's 3 mid-layer bias vectors into smem (parallel, independent)
            #pragma unroll
            for (int lj = 0; lj < NMID; ++lj)
                bms[lj * 256 + tid] = __ldg(bm + (size_t)(b * NMID + lj) * HDIM + tid);
            #pragma unroll 4
            for (int p = 0; p < MT; ++p) {
                float pre = fmaf(zx[2 * p], w0, fmaf(zx[2 * p + 1], w1, bb));
                float m = pre > 0.f ? 1.f : 0.f;
                split_store(Ahi, Alo, abyte(p,      n), fmaxf(pre, 0.f));
                split_store(Ahi, Alo, abyte(16 + p, n), w0 * m * TS_SEED);
                split_store(Ahi, Alo, abyte(32 + p, n), w1 * m * TS_SEED);
            }
        }
        __syncthreads();   // A ready

        // ---------- 3 mid layers : compensated fp16 mma, B direct from L2/L1 ----------
        #pragma unroll 1
        for (int lj = 0; lj < NMID; ++lj) {
            const int glayer = b * NMID + lj;
            const uint4* Bg = g_Wf + ((size_t)glayer * 16) * 1024 + (w * 4) * 32 + lane;

            float c[3][4][4];   // [h,t0,t1][ntl][reg]
            #pragma unroll
            for (int s = 0; s < 3; ++s)
                #pragma unroll
                for (int ntl = 0; ntl < 4; ++ntl)
                    #pragma unroll
                    for (int r = 0; r < 4; ++r) c[s][ntl][r] = 0.f;

            uint4 bv[4];
            #pragma unroll
            for (int ntl = 0; ntl < 4; ++ntl) bv[ntl] = __ldg(Bg + ntl * 32);

            #pragma unroll 1
            for (int ks = 0; ks < 16; ++ks) {
                uint4 bn[4];
                if (ks < 15) {
                    const uint4* Bn = Bg + (ks + 1) * 1024;
                    #pragma unroll
                    for (int ntl = 0; ntl < 4; ++ntl) bn[ntl] = __ldg(Bn + ntl * 32);
                }
                #pragma unroll
                for (int s = 0; s < 3; ++s) {
                    const int fo = ((s * 16 + ks) * 32 + lane) * 16;
                    uint4 ah = *(const uint4*)(Ahi + fo);
                    uint4 al = *(const uint4*)(Alo + fo);
                    #pragma unroll
                    for (int ntl = 0; ntl < 4; ++ntl) {
                        mma_f16(c[s][ntl], ah, bv[ntl].x, bv[ntl].y);   // hi*hi
                        mma_f16(c[s][ntl], ah, bv[ntl].z, bv[ntl].w);   // hi*lo
                        mma_f16(c[s][ntl], al, bv[ntl].x, bv[ntl].y);   // lo*hi
                    }
                }
                #pragma unroll
                for (int ntl = 0; ntl < 4; ++ntl) bv[ntl] = bn[ntl];
            }

            // biases for my 4 n-tiles, from smem stage (no L2 stall here)
            float2 bb2[4];
            #pragma unroll
            for (int ntl = 0; ntl < 4; ++ntl) {
                int n0 = (w * 4 + ntl) * 8 + 2 * (lane & 3);
                bb2[ntl] = *reinterpret_cast<const float2*>(bms + lj * 256 + n0);
            }
            __syncthreads();   // all warps done reading A

            // epilogue: bias + ReLU on h, mask tangents (rescaled x16), split-write A
            #pragma unroll
            for (int ntl = 0; ntl < 4; ++ntl) {
                int colb = (w * 4 + ntl) * 8 + 2 * (lane & 3);
                float pre0 = c[0][ntl][0] + bb2[ntl].x;
                float pre1 = c[0][ntl][1] + bb2[ntl].y;
                float pre2 = c[0][ntl][2] + bb2[ntl].x;
                float pre3 = c[0][ntl][3] + bb2[ntl].y;
                float m0 = (pre0 > 0.f ? 1.f : 0.f) * TS_LAYER;
                float m1 = (pre1 > 0.f ? 1.f : 0.f) * TS_LAYER;
                float m2 = (pre2 > 0.f ? 1.f : 0.f) * TS_LAYER;
                float m3 = (pre3 > 0.f ? 1.f : 0.f) * TS_LAYER;
                int base = (colb >> 4) * 512 + lane * 16 + (colb & 8);
                float vals[3][4] = {
                    {fmaxf(pre0,0.f), fmaxf(pre1,0.f), fmaxf(pre2,0.f), fmaxf(pre3,0.f)},
                    {c[1][ntl][0]*m0, c[1][ntl][1]*m1, c[1][ntl][2]*m2, c[1][ntl][3]*m3},
                    {c[2][ntl][0]*m0, c[2][ntl][1]*m1, c[2][ntl][2]*m2, c[2][ntl][3]*m3}
                };
                #pragma unroll
                for (int s = 0; s < 3; ++s) {
                    __half h0 = __float2half_rn(vals[s][0]);
                    __half h1 = __float2half_rn(vals[s][1]);
                    __half h2 = __float2half_rn(vals[s][2]);
                    __half h3 = __float2half_rn(vals[s][3]);
                    uint2 hi, lo;
                    hi.x = h2u(h0, h1); hi.y = h2u(h2, h3);
                    lo.x = h2u(__float2half_rn(vals[s][0] - __half2float(h0)),
                               __float2half_rn(vals[s][1] - __half2float(h1)));
                    lo.y = h2u(__float2half_rn(vals[s][2] - __half2float(h2)),
                               __float2half_rn(vals[s][3] - __half2float(h3)));
                    int o = base + s * 8192;
                    *(uint2*)(Ahi + o) = hi;
                    *(uint2*)(Alo + o) = lo;
                }
            }
            __syncthreads();
        }

        // ---------- output layer : 256 -> 2, Jacobian, power series ----------
        if (tid < 128)
            ((float4*)Wos)[tid] = ((const float4*)(Wo + (size_t)b * HDIM * 2))[tid];
        __syncthreads();

        if (tid < 192) {   // 16 pts x 3 states x 2 cols x 2 k-halves
            int p = tid & 15;
            int half = (tid >> 4) & 1;
            int idx = tid >> 5;          // 0..5 = s*2+cc
            int s = idx >> 1, cc = idx & 1;
            int row = s * 16 + p;
            float sum = 0.f;
            int k0 = half * 128;
            #pragma unroll 4
            for (int k = k0; k < k0 + 128; k += 2) {
                int o = abyte(row, k);
                __half2 h2 = *(const __half2*)(Ahi + o);
                __half2 l2 = *(const __half2*)(Alo + o);
                float2 hf = __half22float2(h2);
                float2 lf = __half22float2(l2);
                sum = fmaf(hf.x + lf.x, Wos[2 * k + cc], sum);
                sum = fmaf(hf.y + lf.y, Wos[2 * (k + 1) + cc], sum);
            }
            red[idx * 32 + half * 16 + p] = sum;
        }
        __syncthreads();

        if (tid < MT) {
            int p = tid;
            float bo0 = __ldg(bo + b * 2 + 0);
            float bo1 = __ldg(bo + b * 2 + 1);
            float pre0 = (red[0 * 32 + p] + red[0 * 32 + 16 + p]) + bo0;
            float pre1 = (red[1 * 32 + p] + red[1 * 32 + 16 + p]) + bo1;
            float m0 = pre0 > 0.f ? 1.f : 0.f;
            float m1 = pre1 > 0.f ? 1.f : 0.f;
            float J00 = (red[2 * 32 + p] + red[2 * 32 + 16 + p]) * m0 * TS_INV;
            float J10 = (red[3 * 32 + p] + red[3 * 32 + 16 + p]) * m1 * TS_INV;
            float J01 = (red[4 * 32 + p] + red[4 * 32 + 16 + p]) * m0 * TS_INV;
            float J11 = (red[5 * 32 + p] + red[5 * 32 + 16 + p]) * m1 * TS_INV;
            float v0 = vv[2 * p], v1 = vv[2 * p + 1];
            float w0 = v0, w1 = v1;
            float ldet = 0.f;
            const float coefs[5] = {1.f, -0.5f, 1.f / 3.f, -0.25f, 0.2f};
            #pragma unroll
            for (int k = 0; k < 5; ++k) {
                float nw0 = fmaf(J00, w0, J01 * w1);
                float nw1 = fmaf(J10, w0, J11 * w1);
                w0 = nw0; w1 = nw1;
                ldet = fmaf(coefs[k], fmaf(w0, v0, w1 * v1), ldet);
            }
            dl[p] -= ldet;
            zx[2 * p]     += fmaxf(pre0, 0.f);
            zx[2 * p + 1] += fmaxf(pre1, 0.f);
        }
        __syncthreads();
    }

    if (tid < MT) {
        int g = pbase + tid;
        out[2 * g]         = zx[2 * tid];
        out[2 * g + 1]     = zx[2 * tid + 1];
        out[2 * B_PTS + g] = dl[tid];
    }
}

extern "C" void kernel_launch(void* const* d_in, const int* in_sizes, int n_in,
                              void* d_out, int out_size)
{
    const float* x  = (const float*)d_in[0];
    const float* v  = (const float*)d_in[1];
    const float* Wi = (const float*)d_in[2];
    const float* bi = (const float*)d_in[3];
    const float* Wm = (const float*)d_in[4];
    const float* bm = (const float*)d_in[5];
    const float* Wo = (const float*)d_in[6];
    const float* bo = (const float*)d_in[7];
    float* out = (float*)d_out;

    prep_w_kernel<<<NLAYERS * 16 * 32 * 32 / 256, 256>>>(Wm);

    cudaFuncSetAttribute(eq_resflow_f16,
                         cudaFuncAttributeMaxDynamicSharedMemorySize, SMEM_BYTES);
    eq_resflow_f16<<<B_PTS / MT, NTHREADS, SMEM_BYTES>>>(x, v, Wi, bi, bm, Wo, bo, out);
}

// round 15
// speedup vs baseline: 1.0257x; 1.0257x over previous
#include <cuda_runtime.h>
#include <cuda_fp16.h>
#include <cstdint>

#define B_PTS   131072
#define HDIM    256
#define NBLK    8
#define NMID    3
#define MT      16
#define NTHREADS 256
#define NLAYERS (NBLK * NMID)

// tangent-state scaling (exact powers of two; divided out of J at the end)
#define TS_SEED   16384.f
#define TS_LAYER  16.f
#define TS_INV    (1.f / 67108864.f)   // 2^-26

// ---------------- shared memory byte map (per CTA, 2 CTAs/SM) ----------------
#define OFF_AHI  0            // A hi frags: 3mt x 16ks x 32lane x 16B = 24576
#define OFF_ALO  24576        // A lo frags (fp16 residual)            = 24576
#define OFF_WOS  49152        // 512 floats = 2048 B
#define OFF_ZX   51200        // 32 floats
#define OFF_VV   51328        // 32 floats
#define OFF_DL   51456        // 16 floats
#define OFF_RED  51520        // 192 floats = 768 B (2-half output reduction)
#define SMEM_BYTES 52288

// prepacked B fragments: [layer][ks 16][ntile 32][lane 32] x uint4 {b0hi,b1hi,b0lo,b1lo}
__device__ uint4 g_Wf[(size_t)NLAYERS * 16 * 32 * 32];

// ---------------- helpers ----------------
__device__ __forceinline__ void mma_f16(float c[4], const uint4& a, uint32_t b0, uint32_t b1) {
    asm volatile("mma.sync.aligned.m16n8k16.row.col.f32.f16.f16.f32 "
                 "{%0,%1,%2,%3}, {%4,%5,%6,%7}, {%8,%9}, {%0,%1,%2,%3};"
                 : "+f"(c[0]), "+f"(c[1]), "+f"(c[2]), "+f"(c[3])
                 : "r"(a.x), "r"(a.y), "r"(a.z), "r"(a.w), "r"(b0), "r"(b1));
}
__device__ __forceinline__ uint32_t h2u(__half a, __half b) {
    __half2 h = __halves2half2(a, b);
    return *reinterpret_cast<uint32_t*>(&h);
}
// byte offset of element (row 0..47, k 0..255) inside one A image (hi or lo)
// rows 0-15 = h tile, 16-31 = t0, 32-47 = t1
__device__ __forceinline__ int abyte(int row, int k) {
    int tile = (row >> 4) * 16 + (k >> 4);
    int lane = ((row & 7) << 2) | ((k >> 1) & 3);
    int sub  = ((row & 8) >> 2) | ((k & 8) >> 1) | (k & 1);
    return tile * 512 + lane * 16 + sub * 2;
}
__device__ __forceinline__ void split_store(char* bhi, char* blo, int boff, float v) {
    __half h = __float2half_rn(v);
    __half l = __float2half_rn(v - __half2float(h));
    *(__half*)(bhi + boff) = h;
    *(__half*)(blo + boff) = l;
}

// ---------------- pre-pass: pack Wm into split fp16 B-fragment image ----------------
__global__ void prep_w_kernel(const float* __restrict__ Wm) {
    int g = blockIdx.x * 256 + threadIdx.x;     // 0 .. 393215
    int lane = g & 31;
    int t = g >> 5;
    int ntile = t & 31; t >>= 5;
    int ks    = t & 15; t >>= 4;
    int l     = t;
    int n  = ntile * 8 + (lane >> 2);
    int kb = ks * 16 + 2 * (lane & 3);
    const float* W = Wm + (size_t)l * HDIM * HDIM;
    __half hh[4], ll[4];
    int kk[4] = {kb, kb + 1, kb + 8, kb + 9};
    #pragma unroll
    for (int i = 0; i < 4; ++i) {
        float w = W[(size_t)kk[i] * HDIM + n];
        hh[i] = __float2half_rn(w);
        ll[i] = __float2half_rn(w - __half2float(hh[i]));
    }
    uint4 o;
    o.x = h2u(hh[0], hh[1]);
    o.y = h2u(hh[2], hh[3]);
    o.z = h2u(ll[0], ll[1]);
    o.w = h2u(ll[2], ll[3]);
    g_Wf[g] = o;
}

// ---------------- main kernel : 16 pts/CTA, 2 CTAs/SM ----------------
__global__ void __launch_bounds__(NTHREADS, 2)
eq_resflow_f16(const float* __restrict__ x,  const float* __restrict__ v,
               const float* __restrict__ Wi, const float* __restrict__ bi,
               const float* __restrict__ bm,
               const float* __restrict__ Wo, const float* __restrict__ bo,
               float* __restrict__ out)
{
    extern __shared__ char smem[];
    char* Ahi = smem + OFF_AHI;
    char* Alo = smem + OFF_ALO;
    float* Wos = (float*)(smem + OFF_WOS);
    float* zx  = (float*)(smem + OFF_ZX);
    float* vv  = (float*)(smem + OFF_VV);
    float* dl  = (float*)(smem + OFF_DL);
    float* red = (float*)(smem + OFF_RED);

    const int tid  = threadIdx.x;
    const int w    = tid >> 5;        // 0..7: n-group (4 ntiles each)
    const int lane = tid & 31;
    const int pbase = blockIdx.x * MT;

    if (tid < MT) {
        float2 xx = *reinterpret_cast<const float2*>(x + 2 * (pbase + tid));
        float2 vx = *reinterpret_cast<const float2*>(v + 2 * (pbase + tid));
        zx[2 * tid] = xx.x; zx[2 * tid + 1] = xx.y;
        vv[2 * tid] = vx.x; vv[2 * tid + 1] = vx.y;
        dl[tid] = 0.f;
    }
    __syncthreads();

    for (int b = 0; b < NBLK; ++b) {
        // ---------- layer 0 : 2 -> 256, split-write A frags (tangents scaled 2^14) ----------
        {
            int n = tid;
            float w0 = __ldg(Wi + (size_t)b * 2 * HDIM + n);
            float w1 = __ldg(Wi + (size_t)b * 2 * HDIM + HDIM + n);
            float bb = __ldg(bi + (size_t)b * HDIM + n);
            #pragma unroll 4
            for (int p = 0; p < MT; ++p) {
                float pre = fmaf(zx[2 * p], w0, fmaf(zx[2 * p + 1], w1, bb));
                float m = pre > 0.f ? 1.f : 0.f;
                split_store(Ahi, Alo, abyte(p,      n), fmaxf(pre, 0.f));
                split_store(Ahi, Alo, abyte(16 + p, n), w0 * m * TS_SEED);
                split_store(Ahi, Alo, abyte(32 + p, n), w1 * m * TS_SEED);
            }
        }
        __syncthreads();   // A ready

        // ---------- 3 mid layers : compensated fp16 mma, B direct from L2/L1 ----------
        #pragma unroll 1
        for (int lj = 0; lj < NMID; ++lj) {
            const int glayer = b * NMID + lj;
            const uint4* Bg = g_Wf + ((size_t)glayer * 16) * 1024 + (w * 4) * 32 + lane;

            float c[3][4][4];   // [h,t0,t1][ntl][reg]
            #pragma unroll
            for (int s = 0; s < 3; ++s)
                #pragma unroll
                for (int ntl = 0; ntl < 4; ++ntl)
                    #pragma unroll
                    for (int r = 0; r < 4; ++r) c[s][ntl][r] = 0.f;

            uint4 bv[4];
            #pragma unroll
            for (int ntl = 0; ntl < 4; ++ntl) bv[ntl] = __ldg(Bg + ntl * 32);

            #pragma unroll 1
            for (int ks = 0; ks < 16; ++ks) {
                uint4 bn[4];
                if (ks < 15) {
                    const uint4* Bn = Bg + (ks + 1) * 1024;
                    #pragma unroll
                    for (int ntl = 0; ntl < 4; ++ntl) bn[ntl] = __ldg(Bn + ntl * 32);
                }
                #pragma unroll
                for (int s = 0; s < 3; ++s) {
                    const int fo = ((s * 16 + ks) * 32 + lane) * 16;
                    uint4 ah = *(const uint4*)(Ahi + fo);
                    uint4 al = *(const uint4*)(Alo + fo);
                    #pragma unroll
                    for (int ntl = 0; ntl < 4; ++ntl) {
                        mma_f16(c[s][ntl], ah, bv[ntl].x, bv[ntl].y);   // hi*hi
                        mma_f16(c[s][ntl], ah, bv[ntl].z, bv[ntl].w);   // hi*lo
                        mma_f16(c[s][ntl], al, bv[ntl].x, bv[ntl].y);   // lo*hi
                    }
                }
                #pragma unroll
                for (int ntl = 0; ntl < 4; ++ntl) bv[ntl] = bn[ntl];
            }

            // biases for my 4 n-tiles
            float2 bb2[4];
            #pragma unroll
            for (int ntl = 0; ntl < 4; ++ntl) {
                int n0 = (w * 4 + ntl) * 8 + 2 * (lane & 3);
                bb2[ntl] = *reinterpret_cast<const float2*>(bm + (size_t)glayer * HDIM + n0);
            }
            __syncthreads();   // all warps done reading A

            // epilogue: bias + ReLU on h, mask tangents (rescaled x16), split-write A
            #pragma unroll
            for (int ntl = 0; ntl < 4; ++ntl) {
                int colb = (w * 4 + ntl) * 8 + 2 * (lane & 3);
                float pre0 = c[0][ntl][0] + bb2[ntl].x;
                float pre1 = c[0][ntl][1] + bb2[ntl].y;
                float pre2 = c[0][ntl][2] + bb2[ntl].x;
                float pre3 = c[0][ntl][3] + bb2[ntl].y;
                float m0 = (pre0 > 0.f ? 1.f : 0.f) * TS_LAYER;
                float m1 = (pre1 > 0.f ? 1.f : 0.f) * TS_LAYER;
                float m2 = (pre2 > 0.f ? 1.f : 0.f) * TS_LAYER;
                float m3 = (pre3 > 0.f ? 1.f : 0.f) * TS_LAYER;
                int base = (colb >> 4) * 512 + lane * 16 + (colb & 8);
                float vals[3][4] = {
                    {fmaxf(pre0,0.f), fmaxf(pre1,0.f), fmaxf(pre2,0.f), fmaxf(pre3,0.f)},
                    {c[1][ntl][0]*m0, c[1][ntl][1]*m1, c[1][ntl][2]*m2, c[1][ntl][3]*m3},
                    {c[2][ntl][0]*m0, c[2][ntl][1]*m1, c[2][ntl][2]*m2, c[2][ntl][3]*m3}
                };
                #pragma unroll
                for (int s = 0; s < 3; ++s) {
                    __half h0 = __float2half_rn(vals[s][0]);
                    __half h1 = __float2half_rn(vals[s][1]);
                    __half h2 = __float2half_rn(vals[s][2]);
                    __half h3 = __float2half_rn(vals[s][3]);
                    uint2 hi, lo;
                    hi.x = h2u(h0, h1); hi.y = h2u(h2, h3);
                    lo.x = h2u(__float2half_rn(vals[s][0] - __half2float(h0)),
                               __float2half_rn(vals[s][1] - __half2float(h1)));
                    lo.y = h2u(__float2half_rn(vals[s][2] - __half2float(h2)),
                               __float2half_rn(vals[s][3] - __half2float(h3)));
                    int o = base + s * 8192;
                    *(uint2*)(Ahi + o) = hi;
                    *(uint2*)(Alo + o) = lo;
                }
            }
            __syncthreads();
        }

        // ---------- output layer : 256 -> 2, Jacobian, power series ----------
        if (tid < 128)
            ((float4*)Wos)[tid] = ((const float4*)(Wo + (size_t)b * HDIM * 2))[tid];
        __syncthreads();

        if (tid < 192) {   // 16 pts x 3 states x 2 cols x 2 k-halves
            int p = tid & 15;
            int half = (tid >> 4) & 1;
            int idx = tid >> 5;          // 0..5 = s*2+cc
            int s = idx >> 1, cc = idx & 1;
            int row = s * 16 + p;
            float sum = 0.f;
            int k0 = half * 128;
            #pragma unroll 4
            for (int k = k0; k < k0 + 128; k += 2) {
                int o = abyte(row, k);
                __half2 h2 = *(const __half2*)(Ahi + o);
                __half2 l2 = *(const __half2*)(Alo + o);
                float2 hf = __half22float2(h2);
                float2 lf = __half22float2(l2);
                sum = fmaf(hf.x + lf.x, Wos[2 * k + cc], sum);
                sum = fmaf(hf.y + lf.y, Wos[2 * (k + 1) + cc], sum);
            }
            red[idx * 32 + half * 16 + p] = sum;
        }
        __syncthreads();

        if (tid < MT) {
            int p = tid;
            float bo0 = __ldg(bo + b * 2 + 0);
            float bo1 = __ldg(bo + b * 2 + 1);
            float pre0 = (red[0 * 32 + p] + red[0 * 32 + 16 + p]) + bo0;
            float pre1 = (red[1 * 32 + p] + red[1 * 32 + 16 + p]) + bo1;
            float m0 = pre0 > 0.f ? 1.f : 0.f;
            float m1 = pre1 > 0.f ? 1.f : 0.f;
            float J00 = (red[2 * 32 + p] + red[2 * 32 + 16 + p]) * m0 * TS_INV;
            float J10 = (red[3 * 32 + p] + red[3 * 32 + 16 + p]) * m1 * TS_INV;
            float J01 = (red[4 * 32 + p] + red[4 * 32 + 16 + p]) * m0 * TS_INV;
            float J11 = (red[5 * 32 + p] + red[5 * 32 + 16 + p]) * m1 * TS_INV;
            float v0 = vv[2 * p], v1 = vv[2 * p + 1];
            float w0 = v0, w1 = v1;
            float ldet = 0.f;
            const float coefs[5] = {1.f, -0.5f, 1.f / 3.f, -0.25f, 0.2f};
            #pragma unroll
            for (int k = 0; k < 5; ++k) {
                float nw0 = fmaf(J00, w0, J01 * w1);
                float nw1 = fmaf(J10, w0, J11 * w1);
                w0 = nw0; w1 = nw1;
                ldet = fmaf(coefs[k], fmaf(w0, v0, w1 * v1), ldet);
            }
            dl[p] -= ldet;
            zx[2 * p]     += fmaxf(pre0, 0.f);
            zx[2 * p + 1] += fmaxf(pre1, 0.f);
        }
        __syncthreads();
    }

    if (tid < MT) {
        int g = pbase + tid;
        out[2 * g]         = zx[2 * tid];
        out[2 * g + 1]     = zx[2 * tid + 1];
        out[2 * B_PTS + g] = dl[tid];
    }
}

extern "C" void kernel_launch(void* const* d_in, const int* in_sizes, int n_in,
                              void* d_out, int out_size)
{
    const float* x  = (const float*)d_in[0];
    const float* v  = (const float*)d_in[1];
    const float* Wi = (const float*)d_in[2];
    const float* bi = (const float*)d_in[3];
    const float* Wm = (const float*)d_in[4];
    const float* bm = (const float*)d_in[5];
    const float* Wo = (const float*)d_in[6];
    const float* bo = (const float*)d_in[7];
    float* out = (float*)d_out;

    prep_w_kernel<<<NLAYERS * 16 * 32 * 32 / 256, 256>>>(Wm);

    cudaFuncSetAttribute(eq_resflow_f16,
                         cudaFuncAttributeMaxDynamicSharedMemorySize, SMEM_BYTES);
    eq_resflow_f16<<<B_PTS / MT, NTHREADS, SMEM_BYTES>>>(x, v, Wi, bi, bm, Wo, bo, out);
}

// round 16
// speedup vs baseline: 1.2063x; 1.1761x over previous
#include <cuda_runtime.h>
#include <cuda_fp16.h>
#include <cstdint>

#define B_PTS   131072
#define HDIM    256
#define NBLK    8
#define NMID    3
#define MT      16
#define NTHREADS 256
#define NLAYERS (NBLK * NMID)

// tangent-state scaling (exact powers of two; divided out of J at the end)
#define TS_SEED   16384.f
#define TS_LAYER  16.f
#define TS_INV    (1.f / 67108864.f)   // 2^-26

// ---------------- shared memory byte map (per CTA, 2 CTAs/SM) ----------------
#define OFF_AHI  0            // A hi frags: 3mt x 16ks x 32lane x 16B = 24576
#define OFF_ALO  24576        // A lo frags (fp16 residual)            = 24576
#define OFF_REDP 49152        // output partials: 8 warps x 96 floats = 3072 B
#define OFF_RED2 52224        // summed: 96 floats = 384 B
#define OFF_ZX   52608        // 32 floats
#define OFF_VV   52736        // 32 floats
#define OFF_DL   52864        // 16 floats
#define SMEM_BYTES 52928

// prepacked B fragments: [layer][ks 16][ntile 32][lane 32] x uint4 {b0hi,b1hi,b0lo,b1lo}
__device__ uint4 g_Wf[(size_t)NLAYERS * 16 * 32 * 32];
// prepacked Wo fragments: [blk 8][ks 16][lane 32] x uint4 (n=8 tile, cols>=2 zero)
__device__ uint4 g_WoF[NBLK * 16 * 32];

// ---------------- helpers ----------------
__device__ __forceinline__ void mma_f16(float c[4], const uint4& a, uint32_t b0, uint32_t b1) {
    asm volatile("mma.sync.aligned.m16n8k16.row.col.f32.f16.f16.f32 "
                 "{%0,%1,%2,%3}, {%4,%5,%6,%7}, {%8,%9}, {%0,%1,%2,%3};"
                 : "+f"(c[0]), "+f"(c[1]), "+f"(c[2]), "+f"(c[3])
                 : "r"(a.x), "r"(a.y), "r"(a.z), "r"(a.w), "r"(b0), "r"(b1));
}
__device__ __forceinline__ uint32_t h2u(__half a, __half b) {
    __half2 h = __halves2half2(a, b);
    return *reinterpret_cast<uint32_t*>(&h);
}
// byte offset of element (row 0..47, k 0..255) inside one A image (hi or lo)
__device__ __forceinline__ int abyte(int row, int k) {
    int tile = (row >> 4) * 16 + (k >> 4);
    int lane = ((row & 7) << 2) | ((k >> 1) & 3);
    int sub  = ((row & 8) >> 2) | ((k & 8) >> 1) | (k & 1);
    return tile * 512 + lane * 16 + sub * 2;
}
__device__ __forceinline__ void split_store(char* bhi, char* blo, int boff, float v) {
    __half h = __float2half_rn(v);
    __half l = __float2half_rn(v - __half2float(h));
    *(__half*)(bhi + boff) = h;
    *(__half*)(blo + boff) = l;
}

// ---------------- pre-pass: pack Wm into split fp16 B-fragment image ----------------
__global__ void prep_w_kernel(const float* __restrict__ Wm) {
    int g = blockIdx.x * 256 + threadIdx.x;     // 0 .. 393215
    int lane = g & 31;
    int t = g >> 5;
    int ntile = t & 31; t >>= 5;
    int ks    = t & 15; t >>= 4;
    int l     = t;
    int n  = ntile * 8 + (lane >> 2);
    int kb = ks * 16 + 2 * (lane & 3);
    const float* W = Wm + (size_t)l * HDIM * HDIM;
    __half hh[4], ll[4];
    int kk[4] = {kb, kb + 1, kb + 8, kb + 9};
    #pragma unroll
    for (int i = 0; i < 4; ++i) {
        float w = W[(size_t)kk[i] * HDIM + n];
        hh[i] = __float2half_rn(w);
        ll[i] = __float2half_rn(w - __half2float(hh[i]));
    }
    uint4 o;
    o.x = h2u(hh[0], hh[1]);
    o.y = h2u(hh[2], hh[3]);
    o.z = h2u(ll[0], ll[1]);
    o.w = h2u(ll[2], ll[3]);
    g_Wf[g] = o;
}

// ---------------- pre-pass: pack Wo into zero-padded split B-fragments ----------------
__global__ void prep_wo_kernel(const float* __restrict__ Wo) {
    int g = blockIdx.x * 256 + threadIdx.x;     // 0 .. 4095
    int lane = g & 31;
    int ks   = (g >> 5) & 15;
    int blk  = g >> 9;
    int n  = lane >> 2;                          // output col (0..7; >=2 zero)
    int kb = ks * 16 + 2 * (lane & 3);
    const float* W = Wo + (size_t)blk * HDIM * 2;
    __half hh[4], ll[4];
    int kk[4] = {kb, kb + 1, kb + 8, kb + 9};
    #pragma unroll
    for (int i = 0; i < 4; ++i) {
        float w = (n < 2) ? W[(size_t)kk[i] * 2 + n] : 0.f;
        hh[i] = __float2half_rn(w);
        ll[i] = __float2half_rn(w - __half2float(hh[i]));
    }
    uint4 o;
    o.x = h2u(hh[0], hh[1]);
    o.y = h2u(hh[2], hh[3]);
    o.z = h2u(ll[0], ll[1]);
    o.w = h2u(ll[2], ll[3]);
    g_WoF[g] = o;
}

// ---------------- main kernel : 16 pts/CTA, 2 CTAs/SM ----------------
__global__ void __launch_bounds__(NTHREADS, 2)
eq_resflow_f16(const float* __restrict__ x,  const float* __restrict__ v,
               const float* __restrict__ Wi, const float* __restrict__ bi,
               const float* __restrict__ bm,
               const float* __restrict__ bo,
               float* __restrict__ out)
{
    extern __shared__ char smem[];
    char* Ahi = smem + OFF_AHI;
    char* Alo = smem + OFF_ALO;
    float* redP = (float*)(smem + OFF_REDP);
    float* red2 = (float*)(smem + OFF_RED2);
    float* zx  = (float*)(smem + OFF_ZX);
    float* vv  = (float*)(smem + OFF_VV);
    float* dl  = (float*)(smem + OFF_DL);

    const int tid  = threadIdx.x;
    const int w    = tid >> 5;        // 0..7: n-group (4 ntiles each)
    const int lane = tid & 31;
    const int pbase = blockIdx.x * MT;

    if (tid < MT) {
        float2 xx = *reinterpret_cast<const float2*>(x + 2 * (pbase + tid));
        float2 vx = *reinterpret_cast<const float2*>(v + 2 * (pbase + tid));
        zx[2 * tid] = xx.x; zx[2 * tid + 1] = xx.y;
        vv[2 * tid] = vx.x; vv[2 * tid + 1] = vx.y;
        dl[tid] = 0.f;
    }
    __syncthreads();

    for (int b = 0; b < NBLK; ++b) {
        // ---------- layer 0 : 2 -> 256, split-write A frags (tangents scaled 2^14) ----------
        {
            int n = tid;
            float w0 = __ldg(Wi + (size_t)b * 2 * HDIM + n);
            float w1 = __ldg(Wi + (size_t)b * 2 * HDIM + HDIM + n);
            float bb = __ldg(bi + (size_t)b * HDIM + n);
            #pragma unroll 4
            for (int p = 0; p < MT; ++p) {
                float pre = fmaf(zx[2 * p], w0, fmaf(zx[2 * p + 1], w1, bb));
                float m = pre > 0.f ? 1.f : 0.f;
                split_store(Ahi, Alo, abyte(p,      n), fmaxf(pre, 0.f));
                split_store(Ahi, Alo, abyte(16 + p, n), w0 * m * TS_SEED);
                split_store(Ahi, Alo, abyte(32 + p, n), w1 * m * TS_SEED);
            }
        }
        __syncthreads();   // A ready

        // ---------- 3 mid layers : compensated fp16 mma, B direct from L2/L1 ----------
        #pragma unroll 1
        for (int lj = 0; lj < NMID; ++lj) {
            const int glayer = b * NMID + lj;
            const uint4* Bg = g_Wf + ((size_t)glayer * 16) * 1024 + (w * 4) * 32 + lane;

            float c[3][4][4];   // [h,t0,t1][ntl][reg]
            #pragma unroll
            for (int s = 0; s < 3; ++s)
                #pragma unroll
                for (int ntl = 0; ntl < 4; ++ntl)
                    #pragma unroll
                    for (int r = 0; r < 4; ++r) c[s][ntl][r] = 0.f;

            uint4 bv[4];
            #pragma unroll
            for (int ntl = 0; ntl < 4; ++ntl) bv[ntl] = __ldg(Bg + ntl * 32);

            #pragma unroll 1
            for (int ks = 0; ks < 16; ++ks) {
                uint4 bn[4];
                if (ks < 15) {
                    const uint4* Bn = Bg + (ks + 1) * 1024;
                    #pragma unroll
                    for (int ntl = 0; ntl < 4; ++ntl) bn[ntl] = __ldg(Bn + ntl * 32);
                }
                #pragma unroll
                for (int s = 0; s < 3; ++s) {
                    const int fo = ((s * 16 + ks) * 32 + lane) * 16;
                    uint4 ah = *(const uint4*)(Ahi + fo);
                    uint4 al = *(const uint4*)(Alo + fo);
                    #pragma unroll
                    for (int ntl = 0; ntl < 4; ++ntl) {
                        mma_f16(c[s][ntl], ah, bv[ntl].x, bv[ntl].y);   // hi*hi
                        mma_f16(c[s][ntl], ah, bv[ntl].z, bv[ntl].w);   // hi*lo
                        mma_f16(c[s][ntl], al, bv[ntl].x, bv[ntl].y);   // lo*hi
                    }
                }
                #pragma unroll
                for (int ntl = 0; ntl < 4; ++ntl) bv[ntl] = bn[ntl];
            }

            // biases for my 4 n-tiles
            float2 bb2[4];
            #pragma unroll
            for (int ntl = 0; ntl < 4; ++ntl) {
                int n0 = (w * 4 + ntl) * 8 + 2 * (lane & 3);
                bb2[ntl] = *reinterpret_cast<const float2*>(bm + (size_t)glayer * HDIM + n0);
            }
            __syncthreads();   // all warps done reading A

            // epilogue: bias + ReLU on h, mask tangents (rescaled x16), split-write A
            #pragma unroll
            for (int ntl = 0; ntl < 4; ++ntl) {
                int colb = (w * 4 + ntl) * 8 + 2 * (lane & 3);
                float pre0 = c[0][ntl][0] + bb2[ntl].x;
                float pre1 = c[0][ntl][1] + bb2[ntl].y;
                float pre2 = c[0][ntl][2] + bb2[ntl].x;
                float pre3 = c[0][ntl][3] + bb2[ntl].y;
                float m0 = (pre0 > 0.f ? 1.f : 0.f) * TS_LAYER;
                float m1 = (pre1 > 0.f ? 1.f : 0.f) * TS_LAYER;
                float m2 = (pre2 > 0.f ? 1.f : 0.f) * TS_LAYER;
                float m3 = (pre3 > 0.f ? 1.f : 0.f) * TS_LAYER;
                int base = (colb >> 4) * 512 + lane * 16 + (colb & 8);
                float vals[3][4] = {
                    {fmaxf(pre0,0.f), fmaxf(pre1,0.f), fmaxf(pre2,0.f), fmaxf(pre3,0.f)},
                    {c[1][ntl][0]*m0, c[1][ntl][1]*m1, c[1][ntl][2]*m2, c[1][ntl][3]*m3},
                    {c[2][ntl][0]*m0, c[2][ntl][1]*m1, c[2][ntl][2]*m2, c[2][ntl][3]*m3}
                };
                #pragma unroll
                for (int s = 0; s < 3; ++s) {
                    __half h0 = __float2half_rn(vals[s][0]);
                    __half h1 = __float2half_rn(vals[s][1]);
                    __half h2 = __float2half_rn(vals[s][2]);
                    __half h3 = __float2half_rn(vals[s][3]);
                    uint2 hi, lo;
                    hi.x = h2u(h0, h1); hi.y = h2u(h2, h3);
                    lo.x = h2u(__float2half_rn(vals[s][0] - __half2float(h0)),
                               __float2half_rn(vals[s][1] - __half2float(h1)));
                    lo.y = h2u(__float2half_rn(vals[s][2] - __half2float(h2)),
                               __float2half_rn(vals[s][3] - __half2float(h3)));
                    int o = base + s * 8192;
                    *(uint2*)(Ahi + o) = hi;
                    *(uint2*)(Alo + o) = lo;
                }
            }
            __syncthreads();
        }

        // ---------- output layer 256 -> 2 on tensor pipe: per-warp k-slice partials ----------
        {
            float co[3][4];
            #pragma unroll
            for (int s = 0; s < 3; ++s)
                #pragma unroll
                for (int r = 0; r < 4; ++r) co[s][r] = 0.f;

            const uint4* WoF = g_WoF + (b * 16 + w * 2) * 32 + lane;
            #pragma unroll
            for (int kk = 0; kk < 2; ++kk) {
                uint4 wb = WoF[kk * 32];
                int ks = w * 2 + kk;
                #pragma unroll
                for (int s = 0; s < 3; ++s) {
                    const int fo = ((s * 16 + ks) * 32 + lane) * 16;
                    uint4 ah = *(const uint4*)(Ahi + fo);
                    uint4 al = *(const uint4*)(Alo + fo);
                    mma_f16(co[s], ah, wb.x, wb.y);   // hi*hi
                    mma_f16(co[s], ah, wb.z, wb.w);   // hi*lo
                    mma_f16(co[s], al, wb.x, wb.y);   // lo*hi
                }
            }
            if ((lane & 3) == 0) {
                int row = lane >> 2;   // 0..7
                #pragma unroll
                for (int s = 0; s < 3; ++s) {
                    redP[w * 96 + (s * 2 + 0) * 16 + row]     = co[s][0];
                    redP[w * 96 + (s * 2 + 1) * 16 + row]     = co[s][1];
                    redP[w * 96 + (s * 2 + 0) * 16 + row + 8] = co[s][2];
                    redP[w * 96 + (s * 2 + 1) * 16 + row + 8] = co[s][3];
                }
            }
        }
        __syncthreads();

        if (tid < 96) {    // sum 8 warp partials
            int p = tid & 15, idx = tid >> 4;
            float sum = 0.f;
            #pragma unroll
            for (int ww = 0; ww < 8; ++ww) sum += redP[ww * 96 + idx * 16 + p];
            red2[idx * 16 + p] = sum;
        }
        __syncthreads();

        if (tid < MT) {
            int p = tid;
            float bo0 = __ldg(bo + b * 2 + 0);
            float bo1 = __ldg(bo + b * 2 + 1);
            float pre0 = red2[0 * 16 + p] + bo0;
            float pre1 = red2[1 * 16 + p] + bo1;
            float m0 = pre0 > 0.f ? 1.f : 0.f;
            float m1 = pre1 > 0.f ? 1.f : 0.f;
            float J00 = red2[2 * 16 + p] * m0 * TS_INV;
            float J10 = red2[3 * 16 + p] * m1 * TS_INV;
            float J01 = red2[4 * 16 + p] * m0 * TS_INV;
            float J11 = red2[5 * 16 + p] * m1 * TS_INV;
            float v0 = vv[2 * p], v1 = vv[2 * p + 1];
            float w0 = v0, w1 = v1;
            float ldet = 0.f;
            const float coefs[5] = {1.f, -0.5f, 1.f / 3.f, -0.25f, 0.2f};
            #pragma unroll
            for (int k = 0; k < 5; ++k) {
                float nw0 = fmaf(J00, w0, J01 * w1);
                float nw1 = fmaf(J10, w0, J11 * w1);
                w0 = nw0; w1 = nw1;
                ldet = fmaf(coefs[k], fmaf(w0, v0, w1 * v1), ldet);
            }
            dl[p] -= ldet;
            zx[2 * p]     += fmaxf(pre0, 0.f);
            zx[2 * p + 1] += fmaxf(pre1, 0.f);
        }
        __syncthreads();
    }

    if (tid < MT) {
        int g = pbase + tid;
        out[2 * g]         = zx[2 * tid];
        out[2 * g + 1]     = zx[2 * tid + 1];
        out[2 * B_PTS + g] = dl[tid];
    }
}

extern "C" void kernel_launch(void* const* d_in, const int* in_sizes, int n_in,
                              void* d_out, int out_size)
{
    const float* x  = (const float*)d_in[0];
    const float* v  = (const float*)d_in[1];
    const float* Wi = (const float*)d_in[2];
    const float* bi = (const float*)d_in[3];
    const float* Wm = (const float*)d_in[4];
    const float* bm = (const float*)d_in[5];
    const float* Wo = (const float*)d_in[6];
    const float* bo = (const float*)d_in[7];
    float* out = (float*)d_out;

    prep_w_kernel<<<NLAYERS * 16 * 32 * 32 / 256, 256>>>(Wm);
    prep_wo_kernel<<<NBLK * 16 * 32 / 256, 256>>>(Wo);

    cudaFuncSetAttribute(eq_resflow_f16,
                         cudaFuncAttributeMaxDynamicSharedMemorySize, SMEM_BYTES);
    eq_resflow_f16<<<B_PTS / MT, NTHREADS, SMEM_BYTES>>>(x, v, Wi, bi, bm, bo, out);
}